// round 5
// baseline (speedup 1.0000x reference)
#include <cuda_runtime.h>

#define H 128
#define MAXP 25000
#define MAXE 600000
#define BR 64            // rows per block in fused kernel

// Device-global scratch (allocations forbidden). Zero at load; counters are
// re-zeroed each launch by the kernel that consumes them -> replay-safe.
__device__ int g_pcnt[MAXP], g_scnt[MAXP];
__device__ int g_poff[MAXP + 1], g_soff[MAXP + 1];
__device__ int g_pcur[MAXP], g_scur[MAXP];
__device__ int g_pesrc[MAXE], g_sesrc[MAXE];
__device__ __align__(16) float g_wt[H * H];   // g_wt[k*H + c] = W[c*H + k]

// ---------------------------------------------------------------------------
// Phase 1: copy rows [n_prop, n_nodes) of prop_z -> out; degree histograms;
// transpose W into g_wt.
__global__ void k_pre(const float4* __restrict__ src, float4* __restrict__ dst,
                      int off4, int n4copy,
                      const int* __restrict__ pdst, const int* __restrict__ sdst,
                      int ep, int es, const float* __restrict__ W) {
    int i = blockIdx.x * blockDim.x + threadIdx.x;
    if (i < n4copy) dst[off4 + i] = src[off4 + i];
    if (i < ep) atomicAdd(&g_pcnt[pdst[i]], 1);
    else {
        int j = i - ep;
        if (j < es) atomicAdd(&g_scnt[sdst[j]], 1);
    }
    if (i < H * H) {
        int k = i >> 7, c = i & 127;
        g_wt[i] = W[c * H + k];       // read coalesced over k per c? (c fixed per 128 i's)
    }
}

// ---------------------------------------------------------------------------
// Phase 2: single-kernel exclusive scan (grid=2, one block per edge set).
// Zeroes the histogram after reading.
__global__ void k_scan(int n) {
    int* cnt = blockIdx.x ? g_scnt : g_pcnt;
    int* off = blockIdx.x ? g_soff : g_poff;
    int* cur = blockIdx.x ? g_scur : g_pcur;
    const int PER = 25;                 // covers n <= 25600
    int t = threadIdx.x;
    int base = t * PER;
    int loc[PER];
    int sum = 0;
#pragma unroll
    for (int j = 0; j < PER; j++) {
        int idx = base + j;
        int v = (idx < n) ? cnt[idx] : 0;
        loc[j] = sum;
        sum += v;
    }
    int lane = t & 31, w = t >> 5;
    int x = sum;
#pragma unroll
    for (int o = 1; o < 32; o <<= 1) {
        int u = __shfl_up_sync(0xFFFFFFFFu, x, o);
        if (lane >= o) x += u;
    }
    __shared__ int ws[32];
    if (lane == 31) ws[w] = x;
    __syncthreads();
    if (w == 0) {
        int tt = ws[lane];
#pragma unroll
        for (int o = 1; o < 32; o <<= 1) {
            int u = __shfl_up_sync(0xFFFFFFFFu, tt, o);
            if (lane >= o) tt += u;
        }
        ws[lane] = tt;
    }
    __syncthreads();
    int excl = x - sum + (w ? ws[w - 1] : 0);
#pragma unroll
    for (int j = 0; j < PER; j++) {
        int idx = base + j;
        if (idx < n) {
            int o = excl + loc[j];
            off[idx] = o;
            cur[idx] = o;
            cnt[idx] = 0;               // reset for next replay
        }
    }
    if (t == 1023) off[n] = excl + sum;
}

// ---------------------------------------------------------------------------
// Phase 3: fill CSR edge lists via cursor atomics.
__global__ void k_fill(const int* __restrict__ psrc, const int* __restrict__ pdst,
                       const int* __restrict__ ssrc, const int* __restrict__ sdst,
                       int ep, int es) {
    int i = blockIdx.x * blockDim.x + threadIdx.x;
    if (i < ep) {
        int p = atomicAdd(&g_pcur[pdst[i]], 1);
        g_pesrc[p] = psrc[i];
    } else {
        int j = i - ep;
        if (j < es) {
            int p = atomicAdd(&g_scur[sdst[j]], 1);
            g_sesrc[p] = ssrc[j];
        }
    }
}

// ---------------------------------------------------------------------------
// Warp-level CSR row gather: acc(lane) = sum over edges of src[s][lane*4..+3]
__device__ __forceinline__ float4 gather_row(const float* __restrict__ src,
                                             const int* __restrict__ esrc,
                                             int beg, int end, int lane) {
    float4 acc = make_float4(0.f, 0.f, 0.f, 0.f);
    for (int base = beg; base < end; base += 32) {
        int cnt = end - base;
        if (cnt > 32) cnt = 32;
        int sidx = (lane < cnt) ? esrc[base + lane] : 0;
        int j = 0;
        for (; j + 4 <= cnt; j += 4) {
            int s0 = __shfl_sync(0xFFFFFFFFu, sidx, j);
            int s1 = __shfl_sync(0xFFFFFFFFu, sidx, j + 1);
            int s2 = __shfl_sync(0xFFFFFFFFu, sidx, j + 2);
            int s3 = __shfl_sync(0xFFFFFFFFu, sidx, j + 3);
            float4 a = __ldg(reinterpret_cast<const float4*>(src + (size_t)s0 * H) + lane);
            float4 b = __ldg(reinterpret_cast<const float4*>(src + (size_t)s1 * H) + lane);
            float4 c = __ldg(reinterpret_cast<const float4*>(src + (size_t)s2 * H) + lane);
            float4 f = __ldg(reinterpret_cast<const float4*>(src + (size_t)s3 * H) + lane);
            acc.x += (a.x + b.x) + (c.x + f.x);
            acc.y += (a.y + b.y) + (c.y + f.y);
            acc.z += (a.z + b.z) + (c.z + f.z);
            acc.w += (a.w + b.w) + (c.w + f.w);
        }
        for (; j < cnt; j++) {
            int s = __shfl_sync(0xFFFFFFFFu, sidx, j);
            float4 a = __ldg(reinterpret_cast<const float4*>(src + (size_t)s * H) + lane);
            acc.x += a.x; acc.y += a.y; acc.z += a.z; acc.w += a.w;
        }
    }
    return acc;
}

// ---------------------------------------------------------------------------
// Phase 4 (fused): block owns BR=64 rows.
//   1) parent gather -> As[64][132] (warp w: rows w*8..w*8+7)
//   2) block GEMM: acc[8][4] per thread, W tiled 16x132 from g_wt (L2-hot)
//   3) upd = relu(acc+bias) -> back into As
//   4) sibling gather + single write: out = prop_z + sib + upd
// Static smem 42.2KB < 48KB default -> no opt-in attribute needed.
__global__ void __launch_bounds__(256) k_fused(const float* __restrict__ prop_z,
                                               const float* __restrict__ mol_z,
                                               const float* __restrict__ bias,
                                               float* __restrict__ out, int n_prop) {
    __shared__ float As[BR][H + 4];     // 64 x 132
    __shared__ float Ws[16][H + 4];     // 16 x 132
    int tid = threadIdx.x;
    int lane = tid & 31;
    int w = tid >> 5;                   // 0..7
    int row0 = blockIdx.x * BR;

    // --- phase 1: parent gather into As ---
#pragma unroll 1
    for (int r = 0; r < 8; r++) {
        int row = row0 + w * 8 + r;
        float4 acc = make_float4(0.f, 0.f, 0.f, 0.f);
        if (row < n_prop)
            acc = gather_row(prop_z, g_pesrc, g_poff[row], g_poff[row + 1], lane);
        *reinterpret_cast<float4*>(&As[w * 8 + r][lane * 4]) = acc;
    }
    __syncthreads();

    // --- phase 2: GEMM. thread (w=rg, lane=cg): rows rg*8..+7, cols cg*4..+3 ---
    float acc[8][4];
#pragma unroll
    for (int i = 0; i < 8; i++)
#pragma unroll
        for (int j = 0; j < 4; j++) acc[i][j] = 0.f;

#pragma unroll 1
    for (int kt = 0; kt < H; kt += 16) {
        for (int i = tid; i < 16 * H; i += 256) {
            int k = i >> 7, c = i & 127;
            Ws[k][c] = g_wt[(kt + k) * H + c];
        }
        __syncthreads();
#pragma unroll
        for (int k = 0; k < 16; k++) {
            float4 wv = *reinterpret_cast<const float4*>(&Ws[k][lane * 4]);
#pragma unroll
            for (int i = 0; i < 8; i++) {
                float a = As[w * 8 + i][kt + k];    // warp-broadcast
                acc[i][0] += a * wv.x;
                acc[i][1] += a * wv.y;
                acc[i][2] += a * wv.z;
                acc[i][3] += a * wv.w;
            }
        }
        __syncthreads();
    }

    // --- phase 3: relu + bias, write upd back into As ---
    float4 b4 = __ldg(reinterpret_cast<const float4*>(bias) + lane);
#pragma unroll
    for (int i = 0; i < 8; i++) {
        float4 u;
        u.x = fmaxf(acc[i][0] + b4.x, 0.f);
        u.y = fmaxf(acc[i][1] + b4.y, 0.f);
        u.z = fmaxf(acc[i][2] + b4.z, 0.f);
        u.w = fmaxf(acc[i][3] + b4.w, 0.f);
        *reinterpret_cast<float4*>(&As[w * 8 + i][lane * 4]) = u;
    }
    __syncthreads();

    // --- phase 4: sibling gather + final write ---
#pragma unroll 1
    for (int r = 0; r < 8; r++) {
        int row = row0 + w * 8 + r;
        if (row >= n_prop) break;
        float4 accS = gather_row(mol_z, g_sesrc, g_soff[row], g_soff[row + 1], lane);
        float4 p = __ldg(reinterpret_cast<const float4*>(prop_z + (size_t)row * H) + lane);
        float4 u = *reinterpret_cast<const float4*>(&As[w * 8 + r][lane * 4]);
        float4 v;
        v.x = p.x + accS.x + u.x;
        v.y = p.y + accS.y + u.y;
        v.z = p.z + accS.z + u.z;
        v.w = p.w + accS.w + u.w;
        reinterpret_cast<float4*>(out + (size_t)row * H)[lane] = v;
    }
}

extern "C" void kernel_launch(void* const* d_in, const int* in_sizes, int n_in,
                              void* d_out, int out_size) {
    const float* prop_z = (const float*)d_in[0];
    const float* mol_z  = (const float*)d_in[1];
    const float* W      = (const float*)d_in[2];
    const float* b      = (const float*)d_in[3];
    const int* psrc = (const int*)d_in[4];
    const int* pdst = (const int*)d_in[5];
    const int* ssrc = (const int*)d_in[6];
    const int* sdst = (const int*)d_in[7];

    int n_nodes = in_sizes[0] / H;
    int ep      = in_sizes[4];
    int es      = in_sizes[6];
    int n_prop  = in_sizes[8];
    float* out  = (float*)d_out;

    int ne = ep + es;
    int off4 = n_prop * (H / 4);
    int n4copy = (n_nodes - n_prop) * (H / 4);
    int pre_n = n4copy > ne ? n4copy : ne;
    if (pre_n < H * H) pre_n = H * H;
    k_pre<<<(pre_n + 255) / 256, 256>>>((const float4*)prop_z, (float4*)out,
                                        off4, n4copy, pdst, sdst, ep, es, W);

    k_scan<<<2, 1024>>>(n_prop);

    k_fill<<<(ne + 255) / 256, 256>>>(psrc, pdst, ssrc, sdst, ep, es);

    k_fused<<<(n_prop + BR - 1) / BR, 256>>>(prop_z, mol_z, b, out, n_prop);
}

// round 6
// speedup vs baseline: 1.0770x; 1.0770x over previous
#include <cuda_runtime.h>

#define H 128
#define MAXP 25000
#define MAXE 600000
#define BM 64
#define BK 32

// Device-global scratch (allocations forbidden). Zero at load; counters are
// re-zeroed each launch by the kernel that consumes them -> replay-safe.
__device__ __align__(256) float g_agg[MAXP * H];
__device__ int g_pcnt[MAXP], g_scnt[MAXP];
__device__ int g_poff[MAXP + 1], g_soff[MAXP + 1];
__device__ int g_pcur[MAXP], g_scur[MAXP];
__device__ int g_pesrc[MAXE], g_sesrc[MAXE];

// ---------------------------------------------------------------------------
// Phase 1: copy ALL of prop_z -> out; degree histograms.
__global__ void k_pre(const float4* __restrict__ src, float4* __restrict__ dst,
                      int n4,
                      const int* __restrict__ pdst, const int* __restrict__ sdst,
                      int ep, int es) {
    int i = blockIdx.x * blockDim.x + threadIdx.x;
    if (i < n4) dst[i] = src[i];
    if (i < ep) atomicAdd(&g_pcnt[pdst[i]], 1);
    else {
        int j = i - ep;
        if (j < es) atomicAdd(&g_scnt[sdst[j]], 1);
    }
}

// ---------------------------------------------------------------------------
// Phase 2: single-kernel exclusive scan (grid=2). Zeroes histogram after read.
__global__ void k_scan(int n) {
    int* cnt = blockIdx.x ? g_scnt : g_pcnt;
    int* off = blockIdx.x ? g_soff : g_poff;
    int* cur = blockIdx.x ? g_scur : g_pcur;
    const int PER = 25;                 // covers n <= 25600
    int t = threadIdx.x;
    int base = t * PER;
    int loc[PER];
    int sum = 0;
#pragma unroll
    for (int j = 0; j < PER; j++) {
        int idx = base + j;
        int v = (idx < n) ? cnt[idx] : 0;
        loc[j] = sum;
        sum += v;
    }
    int lane = t & 31, w = t >> 5;
    int x = sum;
#pragma unroll
    for (int o = 1; o < 32; o <<= 1) {
        int u = __shfl_up_sync(0xFFFFFFFFu, x, o);
        if (lane >= o) x += u;
    }
    __shared__ int ws[32];
    if (lane == 31) ws[w] = x;
    __syncthreads();
    if (w == 0) {
        int tt = ws[lane];
#pragma unroll
        for (int o = 1; o < 32; o <<= 1) {
            int u = __shfl_up_sync(0xFFFFFFFFu, tt, o);
            if (lane >= o) tt += u;
        }
        ws[lane] = tt;
    }
    __syncthreads();
    int excl = x - sum + (w ? ws[w - 1] : 0);
#pragma unroll
    for (int j = 0; j < PER; j++) {
        int idx = base + j;
        if (idx < n) {
            int o = excl + loc[j];
            off[idx] = o;
            cur[idx] = o;
            cnt[idx] = 0;               // reset for next replay
        }
    }
    if (t == 1023) off[n] = excl + sum;
}

// ---------------------------------------------------------------------------
// Phase 3: fill CSR edge lists via cursor atomics.
__global__ void k_fill(const int* __restrict__ psrc, const int* __restrict__ pdst,
                       const int* __restrict__ ssrc, const int* __restrict__ sdst,
                       int ep, int es) {
    int i = blockIdx.x * blockDim.x + threadIdx.x;
    if (i < ep) {
        int p = atomicAdd(&g_pcur[pdst[i]], 1);
        g_pesrc[p] = psrc[i];
    } else {
        int j = i - ep;
        if (j < es) {
            int p = atomicAdd(&g_scur[sdst[j]], 1);
            g_sesrc[p] = ssrc[j];
        }
    }
}

// ---------------------------------------------------------------------------
// Warp-level CSR row gather: acc(lane) = sum over edges of src[s][lane*4..+3]
__device__ __forceinline__ float4 gather_row(const float* __restrict__ src,
                                             const int* __restrict__ esrc,
                                             int beg, int end, int lane) {
    float4 acc = make_float4(0.f, 0.f, 0.f, 0.f);
    for (int base = beg; base < end; base += 32) {
        int cnt = end - base;
        if (cnt > 32) cnt = 32;
        int sidx = (lane < cnt) ? esrc[base + lane] : 0;
        int j = 0;
        for (; j + 4 <= cnt; j += 4) {
            int s0 = __shfl_sync(0xFFFFFFFFu, sidx, j);
            int s1 = __shfl_sync(0xFFFFFFFFu, sidx, j + 1);
            int s2 = __shfl_sync(0xFFFFFFFFu, sidx, j + 2);
            int s3 = __shfl_sync(0xFFFFFFFFu, sidx, j + 3);
            float4 a = __ldg(reinterpret_cast<const float4*>(src + (size_t)s0 * H) + lane);
            float4 b = __ldg(reinterpret_cast<const float4*>(src + (size_t)s1 * H) + lane);
            float4 c = __ldg(reinterpret_cast<const float4*>(src + (size_t)s2 * H) + lane);
            float4 f = __ldg(reinterpret_cast<const float4*>(src + (size_t)s3 * H) + lane);
            acc.x += (a.x + b.x) + (c.x + f.x);
            acc.y += (a.y + b.y) + (c.y + f.y);
            acc.z += (a.z + b.z) + (c.z + f.z);
            acc.w += (a.w + b.w) + (c.w + f.w);
        }
        for (; j < cnt; j++) {
            int s = __shfl_sync(0xFFFFFFFFu, sidx, j);
            float4 a = __ldg(reinterpret_cast<const float4*>(src + (size_t)s * H) + lane);
            acc.x += a.x; acc.y += a.y; acc.z += a.z; acc.w += a.w;
        }
    }
    return acc;
}

__device__ __forceinline__ void red_add4(float* p, float4 v) {
    asm volatile("red.global.add.v4.f32 [%0], {%1,%2,%3,%4};"
                 :: "l"(p), "f"(v.x), "f"(v.y), "f"(v.z), "f"(v.w)
                 : "memory");
}

// ---------------------------------------------------------------------------
// Phase 4: parent gather -> g_agg. One warp per row (massive MLP, proven shape).
__global__ void k_gpar(const float* __restrict__ prop_z, int n_prop) {
    int gw = (blockIdx.x * blockDim.x + threadIdx.x) >> 5;
    int lane = threadIdx.x & 31;
    if (gw >= n_prop) return;
    float4 acc = gather_row(prop_z, g_pesrc, g_poff[gw], g_poff[gw + 1], lane);
    reinterpret_cast<float4*>(g_agg + (size_t)gw * H)[lane] = acc;
}

// ---------------------------------------------------------------------------
// Phase 5 (block-specialized): blocks [0,G) = GEMM (FFMA-bound),
// blocks [G,...) = sibling gather (L2-bound). Both RED-add into out, so they
// are order-independent and overlap on the chip.
__global__ void __launch_bounds__(128) k_post(const float* __restrict__ W,
                                              const float* __restrict__ bias,
                                              const float* __restrict__ mol_z,
                                              float* __restrict__ out,
                                              int n_prop, int G) {
    int tid = threadIdx.x;
    if ((int)blockIdx.x >= G) {
        // ---- sibling gather: 4 warps, one row each ----
        int row = (blockIdx.x - G) * 4 + (tid >> 5);
        int lane = tid & 31;
        if (row >= n_prop) return;
        float4 acc = gather_row(mol_z, g_sesrc, g_soff[row], g_soff[row + 1], lane);
        red_add4(out + (size_t)row * H + lane * 4, acc);
        return;
    }

    // ---- GEMM: out[r] += relu(g_agg[r] @ W^T + b), 8x8 register tiled ----
    __shared__ float As[BK][BM + 1];    // 32 x 65
    __shared__ float Ws[BK][H + 4];     // 32 x 132
    int cg = tid & 15;                  // columns cg*8 .. cg*8+7
    int rg = tid >> 4;                  // rows    rg*8 .. rg*8+7
    int row0 = blockIdx.x * BM;

    float acc[8][8];
#pragma unroll
    for (int i = 0; i < 8; i++)
#pragma unroll
        for (int j = 0; j < 8; j++) acc[i][j] = 0.f;

#pragma unroll 1
    for (int kt = 0; kt < H; kt += BK) {
#pragma unroll
        for (int idx = tid; idx < BM * BK; idx += 128) {
            int r = idx >> 5, kk = idx & 31;
            int rr = row0 + r;
            As[kk][r] = (rr < n_prop) ? g_agg[rr * H + kt + kk] : 0.f;
        }
#pragma unroll
        for (int idx = tid; idx < H * BK; idx += 128) {
            int c = idx >> 5, kk = idx & 31;
            Ws[kk][c] = W[c * H + kt + kk];
        }
        __syncthreads();
#pragma unroll 8
        for (int k = 0; k < BK; k++) {
            float a[8], w[8];
#pragma unroll
            for (int i = 0; i < 8; i++) a[i] = As[k][rg * 8 + i];
            float4 w0 = *reinterpret_cast<const float4*>(&Ws[k][cg * 8]);
            float4 w1 = *reinterpret_cast<const float4*>(&Ws[k][cg * 8 + 4]);
            w[0] = w0.x; w[1] = w0.y; w[2] = w0.z; w[3] = w0.w;
            w[4] = w1.x; w[5] = w1.y; w[6] = w1.z; w[7] = w1.w;
#pragma unroll
            for (int i = 0; i < 8; i++)
#pragma unroll
                for (int j = 0; j < 8; j++)
                    acc[i][j] += a[i] * w[j];
        }
        __syncthreads();
    }

    float4 b0 = __ldg(reinterpret_cast<const float4*>(bias + cg * 8));
    float4 b1 = __ldg(reinterpret_cast<const float4*>(bias + cg * 8 + 4));

#pragma unroll
    for (int i = 0; i < 8; i++) {
        int rr = row0 + rg * 8 + i;
        if (rr < n_prop) {
            float4 u0, u1;
            u0.x = fmaxf(acc[i][0] + b0.x, 0.f);
            u0.y = fmaxf(acc[i][1] + b0.y, 0.f);
            u0.z = fmaxf(acc[i][2] + b0.z, 0.f);
            u0.w = fmaxf(acc[i][3] + b0.w, 0.f);
            u1.x = fmaxf(acc[i][4] + b1.x, 0.f);
            u1.y = fmaxf(acc[i][5] + b1.y, 0.f);
            u1.z = fmaxf(acc[i][6] + b1.z, 0.f);
            u1.w = fmaxf(acc[i][7] + b1.w, 0.f);
            float* p = out + (size_t)rr * H + cg * 8;
            red_add4(p, u0);
            red_add4(p + 4, u1);
        }
    }
}

extern "C" void kernel_launch(void* const* d_in, const int* in_sizes, int n_in,
                              void* d_out, int out_size) {
    const float* prop_z = (const float*)d_in[0];
    const float* mol_z  = (const float*)d_in[1];
    const float* W      = (const float*)d_in[2];
    const float* b      = (const float*)d_in[3];
    const int* psrc = (const int*)d_in[4];
    const int* pdst = (const int*)d_in[5];
    const int* ssrc = (const int*)d_in[6];
    const int* sdst = (const int*)d_in[7];

    int n_nodes = in_sizes[0] / H;
    int ep      = in_sizes[4];
    int es      = in_sizes[6];
    int n_prop  = in_sizes[8];
    float* out  = (float*)d_out;

    int ne = ep + es;
    int n4 = n_nodes * (H / 4);
    int pre_n = n4 > ne ? n4 : ne;
    k_pre<<<(pre_n + 255) / 256, 256>>>((const float4*)prop_z, (float4*)out,
                                        n4, pdst, sdst, ep, es);

    k_scan<<<2, 1024>>>(n_prop);

    k_fill<<<(ne + 255) / 256, 256>>>(psrc, pdst, ssrc, sdst, ep, es);

    long long gt = (long long)n_prop * 32;
    k_gpar<<<(int)((gt + 255) / 256), 256>>>(prop_z, n_prop);

    int G = (n_prop + BM - 1) / BM;
    int SB = (n_prop + 3) / 4;
    k_post<<<G + SB, 128>>>(W, b, mol_z, out, n_prop, G);
}

// round 7
// speedup vs baseline: 1.2599x; 1.1699x over previous
#include <cuda_runtime.h>

#define H 128
#define MAXP 25000
#define MAXE 600000
#define GBM 128
#define GBK 16

// Device-global scratch (allocations forbidden). Zero at load; counters are
// re-zeroed each launch by the kernel that consumes them -> replay-safe.
__device__ __align__(256) float g_agg[MAXP * H];
__device__ int g_pcnt[MAXP], g_scnt[MAXP];
__device__ int g_poff[MAXP + 1], g_soff[MAXP + 1];
__device__ int g_pcur[MAXP], g_scur[MAXP];
__device__ int g_pesrc[MAXE], g_sesrc[MAXE];

// ---------------------------------------------------------------------------
// Phase 1: copy rows [n_prop, n_nodes) of prop_z -> out; degree histograms.
__global__ void k_pre(const float4* __restrict__ src, float4* __restrict__ dst,
                      int off4, int n4copy,
                      const int* __restrict__ pdst, const int* __restrict__ sdst,
                      int ep, int es) {
    int i = blockIdx.x * blockDim.x + threadIdx.x;
    if (i < n4copy) dst[off4 + i] = src[off4 + i];
    if (i < ep) atomicAdd(&g_pcnt[pdst[i]], 1);
    else {
        int j = i - ep;
        if (j < es) atomicAdd(&g_scnt[sdst[j]], 1);
    }
}

// ---------------------------------------------------------------------------
// Phase 2: single-kernel exclusive scan (grid=2). Zeroes histogram after read.
__global__ void k_scan(int n) {
    int* cnt = blockIdx.x ? g_scnt : g_pcnt;
    int* off = blockIdx.x ? g_soff : g_poff;
    int* cur = blockIdx.x ? g_scur : g_pcur;
    const int PER = 25;
    int t = threadIdx.x;
    int base = t * PER;
    int loc[PER];
    int sum = 0;
#pragma unroll
    for (int j = 0; j < PER; j++) {
        int idx = base + j;
        int v = (idx < n) ? cnt[idx] : 0;
        loc[j] = sum;
        sum += v;
    }
    int lane = t & 31, w = t >> 5;
    int x = sum;
#pragma unroll
    for (int o = 1; o < 32; o <<= 1) {
        int u = __shfl_up_sync(0xFFFFFFFFu, x, o);
        if (lane >= o) x += u;
    }
    __shared__ int ws[32];
    if (lane == 31) ws[w] = x;
    __syncthreads();
    if (w == 0) {
        int tt = ws[lane];
#pragma unroll
        for (int o = 1; o < 32; o <<= 1) {
            int u = __shfl_up_sync(0xFFFFFFFFu, tt, o);
            if (lane >= o) tt += u;
        }
        ws[lane] = tt;
    }
    __syncthreads();
    int excl = x - sum + (w ? ws[w - 1] : 0);
#pragma unroll
    for (int j = 0; j < PER; j++) {
        int idx = base + j;
        if (idx < n) {
            int o = excl + loc[j];
            off[idx] = o;
            cur[idx] = o;
            cnt[idx] = 0;
        }
    }
    if (t == 1023) off[n] = excl + sum;
}

// ---------------------------------------------------------------------------
// Phase 3: fill CSR edge lists via cursor atomics.
__global__ void k_fill(const int* __restrict__ psrc, const int* __restrict__ pdst,
                       const int* __restrict__ ssrc, const int* __restrict__ sdst,
                       int ep, int es) {
    int i = blockIdx.x * blockDim.x + threadIdx.x;
    if (i < ep) {
        int p = atomicAdd(&g_pcur[pdst[i]], 1);
        g_pesrc[p] = psrc[i];
    } else {
        int j = i - ep;
        if (j < es) {
            int p = atomicAdd(&g_scur[sdst[j]], 1);
            g_sesrc[p] = ssrc[j];
        }
    }
}

// ---------------------------------------------------------------------------
// Warp-level CSR row gather.
__device__ __forceinline__ float4 gather_row(const float* __restrict__ src,
                                             const int* __restrict__ esrc,
                                             int beg, int end, int lane) {
    float4 acc = make_float4(0.f, 0.f, 0.f, 0.f);
    for (int base = beg; base < end; base += 32) {
        int cnt = end - base;
        if (cnt > 32) cnt = 32;
        int sidx = (lane < cnt) ? esrc[base + lane] : 0;
        int j = 0;
        for (; j + 4 <= cnt; j += 4) {
            int s0 = __shfl_sync(0xFFFFFFFFu, sidx, j);
            int s1 = __shfl_sync(0xFFFFFFFFu, sidx, j + 1);
            int s2 = __shfl_sync(0xFFFFFFFFu, sidx, j + 2);
            int s3 = __shfl_sync(0xFFFFFFFFu, sidx, j + 3);
            float4 a = __ldg(reinterpret_cast<const float4*>(src + (size_t)s0 * H) + lane);
            float4 b = __ldg(reinterpret_cast<const float4*>(src + (size_t)s1 * H) + lane);
            float4 c = __ldg(reinterpret_cast<const float4*>(src + (size_t)s2 * H) + lane);
            float4 f = __ldg(reinterpret_cast<const float4*>(src + (size_t)s3 * H) + lane);
            acc.x += (a.x + b.x) + (c.x + f.x);
            acc.y += (a.y + b.y) + (c.y + f.y);
            acc.z += (a.z + b.z) + (c.z + f.z);
            acc.w += (a.w + b.w) + (c.w + f.w);
        }
        for (; j < cnt; j++) {
            int s = __shfl_sync(0xFFFFFFFFu, sidx, j);
            float4 a = __ldg(reinterpret_cast<const float4*>(src + (size_t)s * H) + lane);
            acc.x += a.x; acc.y += a.y; acc.z += a.z; acc.w += a.w;
        }
    }
    return acc;
}

// ---------------------------------------------------------------------------
// Phase 4: both gathers, one warp per (row, edge set). Proven 44.4us shape.
// Parent -> g_agg; sibling -> out[d] = prop_z[d] + acc (fuses prop copy).
__global__ void k_gather(const float* __restrict__ prop_z,
                         const float* __restrict__ mol_z,
                         float* __restrict__ out, int n_prop) {
    int gw = (blockIdx.x * blockDim.x + threadIdx.x) >> 5;
    int lane = threadIdx.x & 31;
    bool sib = gw >= n_prop;
    int d = sib ? gw - n_prop : gw;
    if (d >= n_prop) return;
    const int* off = sib ? g_soff : g_poff;
    const int* esrc = sib ? g_sesrc : g_pesrc;
    const float* src = sib ? mol_z : prop_z;

    float4 acc = gather_row(src, esrc, off[d], off[d + 1], lane);

    if (sib) {
        float4 p = __ldg(reinterpret_cast<const float4*>(prop_z + (size_t)d * H) + lane);
        float4 v;
        v.x = p.x + acc.x; v.y = p.y + acc.y; v.z = p.z + acc.z; v.w = p.w + acc.w;
        reinterpret_cast<float4*>(out + (size_t)d * H)[lane] = v;
    } else {
        reinterpret_cast<float4*>(g_agg + (size_t)d * H)[lane] = acc;
    }
}

// ---------------------------------------------------------------------------
// Phase 5: out[r] += relu(g_agg[r] @ W^T + b). 256 threads, BM=128, 8x8/thread,
// BK=16 double-buffered smem with register-staged prefetch (1 sync per tile).
__global__ void __launch_bounds__(256) k_gemm(const float* __restrict__ W,
                                              const float* __restrict__ bias,
                                              float* __restrict__ out, int n_prop) {
    __shared__ float As[2][GBK][GBM + 4];   // [buf][k][row]
    __shared__ float Ws[2][GBK][H + 4];     // [buf][k][col]
    int tid = threadIdx.x;
    int rg = tid >> 4;                      // 0..15 -> rows rg*8..+7
    int cg = tid & 15;                      // 0..15 -> cols cg*8..+7
    int row0 = blockIdx.x * GBM;

    // loader mapping: float4 item i in [0,512): r = i>>2, q = i&3
    int i0 = tid, i1 = tid + 256;
    int r0l = i0 >> 2, q0 = i0 & 3;
    int r1l = i1 >> 2, q1 = i1 & 3;

    float4 pa0, pa1, pw0, pw1;
    const float4 z4 = make_float4(0.f, 0.f, 0.f, 0.f);

#define LDG_TILE(kt)                                                              \
    {                                                                             \
        int rr0 = row0 + r0l, rr1 = row0 + r1l;                                   \
        pa0 = (rr0 < n_prop) ? *reinterpret_cast<const float4*>(                  \
                  g_agg + (size_t)rr0 * H + (kt) + q0 * 4) : z4;                  \
        pa1 = (rr1 < n_prop) ? *reinterpret_cast<const float4*>(                  \
                  g_agg + (size_t)rr1 * H + (kt) + q1 * 4) : z4;                  \
        pw0 = *reinterpret_cast<const float4*>(W + (size_t)r0l * H + (kt) + q0 * 4); \
        pw1 = *reinterpret_cast<const float4*>(W + (size_t)r1l * H + (kt) + q1 * 4); \
    }

#define STS_TILE(b)                                                               \
    {                                                                             \
        As[b][q0 * 4 + 0][r0l] = pa0.x; As[b][q0 * 4 + 1][r0l] = pa0.y;           \
        As[b][q0 * 4 + 2][r0l] = pa0.z; As[b][q0 * 4 + 3][r0l] = pa0.w;           \
        As[b][q1 * 4 + 0][r1l] = pa1.x; As[b][q1 * 4 + 1][r1l] = pa1.y;           \
        As[b][q1 * 4 + 2][r1l] = pa1.z; As[b][q1 * 4 + 3][r1l] = pa1.w;           \
        Ws[b][q0 * 4 + 0][r0l] = pw0.x; Ws[b][q0 * 4 + 1][r0l] = pw0.y;           \
        Ws[b][q0 * 4 + 2][r0l] = pw0.z; Ws[b][q0 * 4 + 3][r0l] = pw0.w;           \
        Ws[b][q1 * 4 + 0][r1l] = pw1.x; Ws[b][q1 * 4 + 1][r1l] = pw1.y;           \
        Ws[b][q1 * 4 + 2][r1l] = pw1.z; Ws[b][q1 * 4 + 3][r1l] = pw1.w;           \
    }

    float acc[8][8];
#pragma unroll
    for (int i = 0; i < 8; i++)
#pragma unroll
        for (int j = 0; j < 8; j++) acc[i][j] = 0.f;

    LDG_TILE(0);
    STS_TILE(0);
    __syncthreads();

    const int T = H / GBK;                  // 8 tiles
#pragma unroll 1
    for (int t = 0; t < T; t++) {
        int b = t & 1;
        if (t + 1 < T) LDG_TILE((t + 1) * GBK);
#pragma unroll
        for (int k = 0; k < GBK; k++) {
            float4 a0 = *reinterpret_cast<const float4*>(&As[b][k][rg * 8]);
            float4 a1 = *reinterpret_cast<const float4*>(&As[b][k][rg * 8 + 4]);
            float4 w0 = *reinterpret_cast<const float4*>(&Ws[b][k][cg * 8]);
            float4 w1 = *reinterpret_cast<const float4*>(&Ws[b][k][cg * 8 + 4]);
            float a[8] = {a0.x, a0.y, a0.z, a0.w, a1.x, a1.y, a1.z, a1.w};
            float w[8] = {w0.x, w0.y, w0.z, w0.w, w1.x, w1.y, w1.z, w1.w};
#pragma unroll
            for (int i = 0; i < 8; i++)
#pragma unroll
                for (int j = 0; j < 8; j++)
                    acc[i][j] += a[i] * w[j];
        }
        if (t + 1 < T) {
            STS_TILE(!b);
            __syncthreads();
        }
    }

    float4 b0 = __ldg(reinterpret_cast<const float4*>(bias + cg * 8));
    float4 b1 = __ldg(reinterpret_cast<const float4*>(bias + cg * 8 + 4));

#pragma unroll
    for (int i = 0; i < 8; i++) {
        int rr = row0 + rg * 8 + i;
        if (rr < n_prop) {
            float4* o = reinterpret_cast<float4*>(out + (size_t)rr * H + cg * 8);
            float4 v0 = o[0], v1 = o[1];
            v0.x += fmaxf(acc[i][0] + b0.x, 0.f);
            v0.y += fmaxf(acc[i][1] + b0.y, 0.f);
            v0.z += fmaxf(acc[i][2] + b0.z, 0.f);
            v0.w += fmaxf(acc[i][3] + b0.w, 0.f);
            v1.x += fmaxf(acc[i][4] + b1.x, 0.f);
            v1.y += fmaxf(acc[i][5] + b1.y, 0.f);
            v1.z += fmaxf(acc[i][6] + b1.z, 0.f);
            v1.w += fmaxf(acc[i][7] + b1.w, 0.f);
            o[0] = v0; o[1] = v1;
        }
    }
#undef LDG_TILE
#undef STS_TILE
}

extern "C" void kernel_launch(void* const* d_in, const int* in_sizes, int n_in,
                              void* d_out, int out_size) {
    const float* prop_z = (const float*)d_in[0];
    const float* mol_z  = (const float*)d_in[1];
    const float* W      = (const float*)d_in[2];
    const float* b      = (const float*)d_in[3];
    const int* psrc = (const int*)d_in[4];
    const int* pdst = (const int*)d_in[5];
    const int* ssrc = (const int*)d_in[6];
    const int* sdst = (const int*)d_in[7];

    int n_nodes = in_sizes[0] / H;
    int ep      = in_sizes[4];
    int es      = in_sizes[6];
    int n_prop  = in_sizes[8];
    float* out  = (float*)d_out;

    int ne = ep + es;
    int off4 = n_prop * (H / 4);
    int n4copy = (n_nodes - n_prop) * (H / 4);
    int pre_n = n4copy > ne ? n4copy : ne;
    k_pre<<<(pre_n + 255) / 256, 256>>>((const float4*)prop_z, (float4*)out,
                                        off4, n4copy, pdst, sdst, ep, es);

    k_scan<<<2, 1024>>>(n_prop);

    k_fill<<<(ne + 255) / 256, 256>>>(psrc, pdst, ssrc, sdst, ep, es);

    long long gt = (long long)2 * n_prop * 32;
    k_gather<<<(int)((gt + 255) / 256), 256>>>(prop_z, mol_z, out, n_prop);

    k_gemm<<<(n_prop + GBM - 1) / GBM, 256>>>(W, b, out, n_prop);
}